// round 1
// baseline (speedup 1.0000x reference)
#include <cuda_runtime.h>
#include <math.h>

#define N_NODES 100000
#define N_EDGES 1600000
#define FDIM 128
#define NG 64
#define NL 20
#define SCAN_NB 391   // ceil(100000/256)

// ---------------- device scratch (no allocations allowed) ----------------
__device__ float g_h0[N_NODES * FDIM];
__device__ float g_h1[N_NODES * FDIM];
__device__ float g_agg[N_NODES * FDIM];
__device__ int   g_deg[N_NODES];
__device__ int   g_rowstart[N_NODES + 1];
__device__ int   g_cursor[N_NODES];
__device__ int   g_esrc[N_EDGES];
__device__ int   g_blocksums[512];
__device__ int   g_blockoffs[512];
__device__ int   g_gmax[NG * FDIM];     // float bits, values >= 0 so int-max == float-max
__device__ float g_gsum[NG * FDIM];
__device__ int   g_gcnt[NG];
__device__ float g_gvec[NG * 2 * FDIM];
__device__ float g_m1[NG * 128];
__device__ float g_m2[NG * 64];
__device__ float g_z[NG * NL];

// ---------------- embedding gather ----------------
__global__ void k_gather(const int* __restrict__ x, const float4* __restrict__ emb) {
    int idx = blockIdx.x * blockDim.x + threadIdx.x;
    if (idx >= N_NODES * 32) return;
    int node = idx >> 5;
    int c = idx & 31;
    ((float4*)g_h0)[idx] = emb[(size_t)x[node] * 32 + c];
}

// ---------------- CSR build ----------------
__global__ void k_zero_deg() {
    int i = blockIdx.x * blockDim.x + threadIdx.x;
    if (i < N_NODES) g_deg[i] = 0;
}

__global__ void k_count(const int* __restrict__ dst) {
    int e = blockIdx.x * blockDim.x + threadIdx.x;
    if (e < N_EDGES) atomicAdd(&g_deg[dst[e]], 1);
}

__device__ __forceinline__ int block_scan_inc(int v, int* warpbuf) {
    int tid = threadIdx.x, lane = tid & 31, wid = tid >> 5;
#pragma unroll
    for (int off = 1; off < 32; off <<= 1) {
        int t = __shfl_up_sync(0xffffffffu, v, off);
        if (lane >= off) v += t;
    }
    if (lane == 31) warpbuf[wid] = v;
    __syncthreads();
    if (wid == 0) {
        int nw = blockDim.x >> 5;
        int w = (lane < nw) ? warpbuf[lane] : 0;
#pragma unroll
        for (int off = 1; off < 32; off <<= 1) {
            int t = __shfl_up_sync(0xffffffffu, w, off);
            if (lane >= off) w += t;
        }
        warpbuf[lane] = w;
    }
    __syncthreads();
    return v + (wid > 0 ? warpbuf[wid - 1] : 0);
}

__global__ void k_scan1() {
    __shared__ int wb[32];
    int i = blockIdx.x * blockDim.x + threadIdx.x;
    int v = (i < N_NODES) ? g_deg[i] : 0;
    int inc = block_scan_inc(v, wb);
    if (threadIdx.x == blockDim.x - 1) g_blocksums[blockIdx.x] = inc;
}

__global__ void k_scan2() {
    __shared__ int wb[32];
    int tid = threadIdx.x;
    int v = (tid < SCAN_NB) ? g_blocksums[tid] : 0;
    int inc = block_scan_inc(v, wb);
    if (tid < SCAN_NB) g_blockoffs[tid] = inc - v;
    if (tid == SCAN_NB - 1) g_rowstart[N_NODES] = inc;
}

__global__ void k_scan3() {
    __shared__ int wb[32];
    int i = blockIdx.x * blockDim.x + threadIdx.x;
    int v = (i < N_NODES) ? g_deg[i] : 0;
    int inc = block_scan_inc(v, wb);
    if (i < N_NODES) {
        int ex = g_blockoffs[blockIdx.x] + inc - v;
        g_rowstart[i] = ex;
        g_cursor[i] = ex;
    }
}

__global__ void k_fill(const int* __restrict__ src, const int* __restrict__ dst) {
    int e = blockIdx.x * blockDim.x + threadIdx.x;
    if (e >= N_EDGES) return;
    int d = dst[e];
    int pos = atomicAdd(&g_cursor[d], 1);
    g_esrc[pos] = src[e];
}

// ---------------- edge aggregation (gather-sum, warp per node) ----------------
__global__ void k_aggregate(int layer) {
    const float4* __restrict__ hin = (const float4*)(layer ? g_h1 : g_h0);
    int w = (blockIdx.x * blockDim.x + threadIdx.x) >> 5;
    int lane = threadIdx.x & 31;
    if (w >= N_NODES) return;
    int start = g_rowstart[w];
    int end = g_rowstart[w + 1];
    float4 acc = make_float4(0.f, 0.f, 0.f, 0.f);
    for (int e = start; e < end; e += 32) {
        int cnt = min(32, end - e);
        int s = (lane < cnt) ? g_esrc[e + lane] : 0;
        for (int j = 0; j < cnt; j++) {
            int sj = __shfl_sync(0xffffffffu, s, j);
            float4 v = hin[(size_t)sj * 32 + lane];
            acc.x += v.x; acc.y += v.y; acc.z += v.z; acc.w += v.w;
        }
    }
    ((float4*)g_agg)[(size_t)w * 32 + lane] = acc;
}

// ---------------- fused GEMM: out = relu(agg@Wr + h@Wo + b) ----------------
#define GEMM_SMEM ((2 * 16384 + 2 * 4096) * 4)
__global__ void k_gemm(const float* __restrict__ Wr, const float* __restrict__ Wo,
                       const float* __restrict__ bias, int layer) {
    extern __shared__ float sm[];
    float* sWr = sm;
    float* sWo = sm + 16384;
    float* sA  = sm + 32768;
    float* sH  = sm + 36864;
    const float* A = g_agg;
    const float* H = layer ? g_h1 : g_h0;
    float* O       = layer ? g_h0 : g_h1;

    int tid = threadIdx.x;
    for (int i = tid; i < 4096; i += 256) {
        ((float4*)sWr)[i] = ((const float4*)Wr)[i];
        ((float4*)sWo)[i] = ((const float4*)Wo)[i];
    }
    int warp = tid >> 5, lane = tid & 31;
    float4 bv = ((const float4*)bias)[lane];

    for (int tile = blockIdx.x; tile < N_NODES / 32; tile += gridDim.x) {
        int row0 = tile * 32;
        __syncthreads();
        const float4* gA = (const float4*)(A + (size_t)row0 * 128);
        const float4* gH = (const float4*)(H + (size_t)row0 * 128);
        for (int i = tid; i < 1024; i += 256) {
            ((float4*)sA)[i] = gA[i];
            ((float4*)sH)[i] = gH[i];
        }
        __syncthreads();

        float acc[4][4];
#pragma unroll
        for (int r = 0; r < 4; r++) {
            acc[r][0] = bv.x; acc[r][1] = bv.y; acc[r][2] = bv.z; acc[r][3] = bv.w;
        }
        const float* aA = sA + warp * 4 * 128;
        const float* aH = sH + warp * 4 * 128;
#pragma unroll 2
        for (int k = 0; k < 128; k++) {
            float4 wr = ((const float4*)(sWr + k * 128))[lane];
            float4 wo = ((const float4*)(sWo + k * 128))[lane];
#pragma unroll
            for (int r = 0; r < 4; r++) {
                float a1 = aA[r * 128 + k];
                float a2 = aH[r * 128 + k];
                acc[r][0] += a1 * wr.x + a2 * wo.x;
                acc[r][1] += a1 * wr.y + a2 * wo.y;
                acc[r][2] += a1 * wr.z + a2 * wo.z;
                acc[r][3] += a1 * wr.w + a2 * wo.w;
            }
        }
#pragma unroll
        for (int r = 0; r < 4; r++) {
            float4 o;
            o.x = fmaxf(acc[r][0], 0.f);
            o.y = fmaxf(acc[r][1], 0.f);
            o.z = fmaxf(acc[r][2], 0.f);
            o.w = fmaxf(acc[r][3], 0.f);
            ((float4*)(O + (size_t)(row0 + warp * 4 + r) * 128))[lane] = o;
        }
    }
}

// ---------------- pooling (batch is sorted: strip-reduce then few atomics) ----
__global__ void k_pool_init() {
    int i = blockIdx.x * blockDim.x + threadIdx.x;
    if (i < NG * FDIM) { g_gmax[i] = 0; g_gsum[i] = 0.f; }
    if (i < NG) g_gcnt[i] = 0;
}

__device__ __forceinline__ void pool_flush(int gph, int lane, float4 mx, float4 sm, int cnt) {
    int base = gph * FDIM + lane * 4;
    atomicMax(&g_gmax[base + 0], __float_as_int(mx.x));
    atomicMax(&g_gmax[base + 1], __float_as_int(mx.y));
    atomicMax(&g_gmax[base + 2], __float_as_int(mx.z));
    atomicMax(&g_gmax[base + 3], __float_as_int(mx.w));
    atomicAdd(&g_gsum[base + 0], sm.x);
    atomicAdd(&g_gsum[base + 1], sm.y);
    atomicAdd(&g_gsum[base + 2], sm.z);
    atomicAdd(&g_gsum[base + 3], sm.w);
    if (lane == 0) atomicAdd(&g_gcnt[gph], cnt);
}

__global__ void k_pool(const int* __restrict__ batch) {
    const float4* __restrict__ h = (const float4*)g_h0;  // final layer output
    int w = (blockIdx.x * blockDim.x + threadIdx.x) >> 5;
    int lane = threadIdx.x & 31;
    if (w >= N_NODES / 32) return;
    int n0 = w * 32;
    int cur = batch[n0];
    float4 mx = make_float4(0.f, 0.f, 0.f, 0.f);
    float4 sm = make_float4(0.f, 0.f, 0.f, 0.f);
    int cnt = 0;
    for (int i = 0; i < 32; i++) {
        int n = n0 + i;
        int b = batch[n];
        if (b != cur) {
            pool_flush(cur, lane, mx, sm, cnt);
            mx = make_float4(0.f, 0.f, 0.f, 0.f);
            sm = make_float4(0.f, 0.f, 0.f, 0.f);
            cnt = 0;
            cur = b;
        }
        float4 v = h[(size_t)n * 32 + lane];
        mx.x = fmaxf(mx.x, v.x); mx.y = fmaxf(mx.y, v.y);
        mx.z = fmaxf(mx.z, v.z); mx.w = fmaxf(mx.w, v.w);
        sm.x += v.x; sm.y += v.y; sm.z += v.z; sm.w += v.w;
        cnt++;
    }
    pool_flush(cur, lane, mx, sm, cnt);
}

// ---------------- MLP head ----------------
__global__ void k_headg() {
    int gph = blockIdx.x;
    int c = threadIdx.x;
    float v;
    if (c < 128) {
        v = __int_as_float(g_gmax[gph * 128 + c]);
    } else {
        int cnt = g_gcnt[gph];
        float fc = (float)(cnt > 1 ? cnt : 1);
        v = g_gsum[gph * 128 + (c - 128)] / fc;
    }
    g_gvec[gph * 256 + c] = v;
}

__global__ void k_head1(const float* __restrict__ lw1, const float* __restrict__ lb1) {
    __shared__ float row[256];
    int gph = blockIdx.x, c = threadIdx.x;
    row[c] = g_gvec[gph * 256 + c];
    row[c + 128] = g_gvec[gph * 256 + c + 128];
    __syncthreads();
    float acc = lb1[c];
#pragma unroll 8
    for (int k = 0; k < 256; k++) acc += row[k] * lw1[k * 128 + c];
    g_m1[gph * 128 + c] = fmaxf(acc, 0.f);
}

__global__ void k_head2(const float* __restrict__ lw2, const float* __restrict__ lb2) {
    __shared__ float row[128];
    int gph = blockIdx.x, c = threadIdx.x;
    row[c] = g_m1[gph * 128 + c];
    row[c + 64] = g_m1[gph * 128 + c + 64];
    __syncthreads();
    float acc = lb2[c];
#pragma unroll 8
    for (int k = 0; k < 128; k++) acc += row[k] * lw2[k * 64 + c];
    g_m2[gph * 64 + c] = fmaxf(acc, 0.f);
}

__global__ void k_head3(const float* __restrict__ lw3, const float* __restrict__ lb3) {
    int gph = blockIdx.x, l = threadIdx.x;
    if (l >= NL) return;
    float acc = lb3[l];
#pragma unroll 8
    for (int k = 0; k < 64; k++) acc += g_m2[gph * 64 + k] * lw3[k * NL + l];
    g_z[gph * NL + l] = acc;
}

__global__ void k_softmax(float* __restrict__ out) {
    int l = threadIdx.x;
    if (l >= NL) return;
    float m = -1e30f;
    for (int gph = 0; gph < NG; gph++) m = fmaxf(m, g_z[gph * NL + l]);
    float s = 0.f;
    for (int gph = 0; gph < NG; gph++) s += expf(g_z[gph * NL + l] - m);
    float ls = m + logf(s);
    for (int gph = 0; gph < NG; gph++) out[gph * NL + l] = g_z[gph * NL + l] - ls;
}

// ---------------- launch ----------------
extern "C" void kernel_launch(void* const* d_in, const int* in_sizes, int n_in,
                              void* d_out, int out_size) {
    const int*   x       = (const int*)d_in[0];
    const int*   ei      = (const int*)d_in[1];
    const int*   batch   = (const int*)d_in[2];
    const float* emb     = (const float*)d_in[3];
    const float* w1_rel  = (const float*)d_in[4];
    const float* w1_root = (const float*)d_in[5];
    const float* b1      = (const float*)d_in[6];
    const float* w2_rel  = (const float*)d_in[7];
    const float* w2_root = (const float*)d_in[8];
    const float* b2      = (const float*)d_in[9];
    const float* lw1     = (const float*)d_in[10];
    const float* lb1     = (const float*)d_in[11];
    const float* lw2     = (const float*)d_in[12];
    const float* lb2     = (const float*)d_in[13];
    const float* lw3     = (const float*)d_in[14];
    const float* lb3     = (const float*)d_in[15];
    const int* src = ei;
    const int* dst = ei + N_EDGES;
    float* out = (float*)d_out;

    cudaFuncSetAttribute(k_gemm, cudaFuncAttributeMaxDynamicSharedMemorySize, GEMM_SMEM);

    k_gather<<<12500, 256>>>(x, (const float4*)emb);

    // CSR build (shared by both layers)
    k_zero_deg<<<SCAN_NB, 256>>>();
    k_count<<<N_EDGES / 256, 256>>>(dst);
    k_scan1<<<SCAN_NB, 256>>>();
    k_scan2<<<1, 512>>>();
    k_scan3<<<SCAN_NB, 256>>>();
    k_fill<<<N_EDGES / 256, 256>>>(src, dst);

    // layer 1
    k_aggregate<<<12500, 256>>>(0);
    k_gemm<<<148, 256, GEMM_SMEM>>>(w1_rel, w1_root, b1, 0);
    // layer 2
    k_aggregate<<<12500, 256>>>(1);
    k_gemm<<<148, 256, GEMM_SMEM>>>(w2_rel, w2_root, b2, 1);

    // pooling
    k_pool_init<<<32, 256>>>();
    k_pool<<<SCAN_NB, 256>>>(batch);

    // head
    k_headg<<<NG, 256>>>();
    k_head1<<<NG, 128>>>(lw1, lb1);
    k_head2<<<NG, 64>>>(lw2, lb2);
    k_head3<<<NG, 32>>>(lw3, lb3);
    k_softmax<<<1, 32>>>(out);
}

// round 2
// speedup vs baseline: 1.0977x; 1.0977x over previous
#include <cuda_runtime.h>
#include <math.h>

#define N_NODES 100000
#define N_EDGES 1600000
#define FDIM 128
#define NG 64
#define NL 20
#define SCAN_NB 391   // ceil(100000/256)

// ---------------- device scratch (no allocations allowed) ----------------
__device__ float g_h0[N_NODES * FDIM];
__device__ float g_h1[N_NODES * FDIM];
__device__ float g_agg[N_NODES * FDIM];
__device__ int   g_deg[N_NODES];
__device__ int   g_rowstart[N_NODES + 1];
__device__ int   g_cursor[N_NODES];
__device__ int   g_esrc[N_EDGES];
__device__ int   g_blocksums[512];
__device__ int   g_blockoffs[512];
__device__ int   g_gmax[NG * FDIM];     // float bits, values >= 0 so int-max == float-max
__device__ float g_gsum[NG * FDIM];
__device__ int   g_gcnt[NG];
__device__ float g_gvec[NG * 2 * FDIM];
__device__ float g_m1[NG * 128];
__device__ float g_m2[NG * 64];
__device__ float g_z[NG * NL];

// ---------------- f32x2 helpers (FFMA2 path, PTX-only per SASS_QUICKREF) ----
__device__ __forceinline__ unsigned long long pk2(float a) {
    unsigned long long r;
    asm("mov.b64 %0, {%1, %1};" : "=l"(r) : "f"(a));
    return r;
}
__device__ __forceinline__ void fma2(unsigned long long& d, unsigned long long a,
                                     unsigned long long b) {
    asm("fma.rn.f32x2 %0, %1, %2, %0;" : "+l"(d) : "l"(a), "l"(b));
}
__device__ __forceinline__ float2 up2(unsigned long long v) {
    float2 f;
    asm("mov.b64 {%0, %1}, %2;" : "=f"(f.x), "=f"(f.y) : "l"(v));
    return f;
}

// ---------------- embedding gather ----------------
__global__ void k_gather(const int* __restrict__ x, const float4* __restrict__ emb) {
    int idx = blockIdx.x * blockDim.x + threadIdx.x;
    if (idx >= N_NODES * 32) return;
    int node = idx >> 5;
    int c = idx & 31;
    ((float4*)g_h0)[idx] = emb[(size_t)x[node] * 32 + c];
}

// ---------------- CSR build ----------------
__global__ void k_zero_deg() {
    int i = blockIdx.x * blockDim.x + threadIdx.x;
    if (i < N_NODES) g_deg[i] = 0;
}

__global__ void k_count(const int* __restrict__ dst) {
    int e = blockIdx.x * blockDim.x + threadIdx.x;
    if (e < N_EDGES) atomicAdd(&g_deg[dst[e]], 1);
}

__device__ __forceinline__ int block_scan_inc(int v, int* warpbuf) {
    int tid = threadIdx.x, lane = tid & 31, wid = tid >> 5;
#pragma unroll
    for (int off = 1; off < 32; off <<= 1) {
        int t = __shfl_up_sync(0xffffffffu, v, off);
        if (lane >= off) v += t;
    }
    if (lane == 31) warpbuf[wid] = v;
    __syncthreads();
    if (wid == 0) {
        int nw = blockDim.x >> 5;
        int w = (lane < nw) ? warpbuf[lane] : 0;
#pragma unroll
        for (int off = 1; off < 32; off <<= 1) {
            int t = __shfl_up_sync(0xffffffffu, w, off);
            if (lane >= off) w += t;
        }
        warpbuf[lane] = w;
    }
    __syncthreads();
    return v + (wid > 0 ? warpbuf[wid - 1] : 0);
}

__global__ void k_scan1() {
    __shared__ int wb[32];
    int i = blockIdx.x * blockDim.x + threadIdx.x;
    int v = (i < N_NODES) ? g_deg[i] : 0;
    int inc = block_scan_inc(v, wb);
    if (threadIdx.x == blockDim.x - 1) g_blocksums[blockIdx.x] = inc;
}

__global__ void k_scan2() {
    __shared__ int wb[32];
    int tid = threadIdx.x;
    int v = (tid < SCAN_NB) ? g_blocksums[tid] : 0;
    int inc = block_scan_inc(v, wb);
    if (tid < SCAN_NB) g_blockoffs[tid] = inc - v;
    if (tid == SCAN_NB - 1) g_rowstart[N_NODES] = inc;
}

__global__ void k_scan3() {
    __shared__ int wb[32];
    int i = blockIdx.x * blockDim.x + threadIdx.x;
    int v = (i < N_NODES) ? g_deg[i] : 0;
    int inc = block_scan_inc(v, wb);
    if (i < N_NODES) {
        int ex = g_blockoffs[blockIdx.x] + inc - v;
        g_rowstart[i] = ex;
        g_cursor[i] = ex;
    }
}

__global__ void k_fill(const int* __restrict__ src, const int* __restrict__ dst) {
    int e = blockIdx.x * blockDim.x + threadIdx.x;
    if (e >= N_EDGES) return;
    int d = dst[e];
    int pos = atomicAdd(&g_cursor[d], 1);
    g_esrc[pos] = src[e];
}

// ---------------- edge aggregation (gather-sum, warp per node) ----------------
__global__ void k_aggregate(int layer) {
    const float4* __restrict__ hin = (const float4*)(layer ? g_h1 : g_h0);
    int w = (blockIdx.x * blockDim.x + threadIdx.x) >> 5;
    int lane = threadIdx.x & 31;
    if (w >= N_NODES) return;
    int start = g_rowstart[w];
    int end = g_rowstart[w + 1];
    float4 acc = make_float4(0.f, 0.f, 0.f, 0.f);
    for (int e = start; e < end; e += 32) {
        int cnt = min(32, end - e);
        int s = (lane < cnt) ? g_esrc[e + lane] : 0;
        for (int j = 0; j < cnt; j++) {
            int sj = __shfl_sync(0xffffffffu, s, j);
            float4 v = hin[(size_t)sj * 32 + lane];
            acc.x += v.x; acc.y += v.y; acc.z += v.z; acc.w += v.w;
        }
    }
    ((float4*)g_agg)[(size_t)w * 32 + lane] = acc;
}

// ---------------- fused GEMM via FFMA2: out = relu(agg@Wr + h@Wo + b) --------
// 256 threads, persistent blocks. Tile = 64 rows x 128 cols.
// Thread = 4 rows x 8 cols, accumulated as four f32x2 pairs per row.
#define GEMM_TILE 64
#define GEMM_NT   1563  // ceil(100000/64)
#define GEMM_SMEM ((16384 + 16384 + GEMM_TILE * 128 * 2) * 4)

__global__ void __launch_bounds__(256, 1)
k_gemm(const float* __restrict__ Wr, const float* __restrict__ Wo,
       const float* __restrict__ bias, int layer) {
    extern __shared__ float sm[];
    float* sWr = sm;                         // 128x128
    float* sWo = sm + 16384;                 // 128x128
    float* sA  = sm + 32768;                 // 64x128
    float* sH  = sm + 32768 + GEMM_TILE * 128;
    const float* A = g_agg;
    const float* H = layer ? g_h1 : g_h0;
    float* O       = layer ? g_h0 : g_h1;

    int tid = threadIdx.x;
    for (int i = tid; i < 4096; i += 256) {
        ((float4*)sWr)[i] = ((const float4*)Wr)[i];
        ((float4*)sWo)[i] = ((const float4*)Wo)[i];
    }

    int colg = tid & 15;          // 16 groups of 8 cols
    int rowp = tid >> 4;          // 0..15, 4 rows each
    int c0 = colg * 8;
    int r0 = rowp * 4;

    ulonglong2 bv01 = *(const ulonglong2*)(bias + c0);
    ulonglong2 bv23 = *(const ulonglong2*)(bias + c0 + 4);

    for (int tile = blockIdx.x; tile < GEMM_NT; tile += gridDim.x) {
        int row0 = tile * GEMM_TILE;
        __syncthreads();
        const float4* gA = (const float4*)(A + (size_t)row0 * 128);
        const float4* gH = (const float4*)(H + (size_t)row0 * 128);
        for (int i = tid; i < GEMM_TILE * 32; i += 256) {
            if (row0 + (i >> 5) < N_NODES) {
                ((float4*)sA)[i] = gA[i];
                ((float4*)sH)[i] = gH[i];
            }
        }
        __syncthreads();

        unsigned long long acc[4][4];
#pragma unroll
        for (int r = 0; r < 4; r++) {
            acc[r][0] = bv01.x; acc[r][1] = bv01.y;
            acc[r][2] = bv23.x; acc[r][3] = bv23.y;
        }
        const float* aA = sA + r0 * 128;
        const float* aH = sH + r0 * 128;

#pragma unroll 1
        for (int kk = 0; kk < 128; kk += 4) {
            float4 av[4], hv[4];
#pragma unroll
            for (int r = 0; r < 4; r++) {
                av[r] = *(const float4*)(aA + r * 128 + kk);
                hv[r] = *(const float4*)(aH + r * 128 + kk);
            }
#pragma unroll
            for (int j = 0; j < 4; j++) {
                int k = kk + j;
                ulonglong2 wr01 = *(const ulonglong2*)(sWr + k * 128 + c0);
                ulonglong2 wr23 = *(const ulonglong2*)(sWr + k * 128 + c0 + 4);
                ulonglong2 wo01 = *(const ulonglong2*)(sWo + k * 128 + c0);
                ulonglong2 wo23 = *(const ulonglong2*)(sWo + k * 128 + c0 + 4);
#pragma unroll
                for (int r = 0; r < 4; r++) {
                    float a1 = (j == 0) ? av[r].x : (j == 1) ? av[r].y
                             : (j == 2) ? av[r].z : av[r].w;
                    float a2 = (j == 0) ? hv[r].x : (j == 1) ? hv[r].y
                             : (j == 2) ? hv[r].z : hv[r].w;
                    unsigned long long p1 = pk2(a1);
                    unsigned long long p2 = pk2(a2);
                    fma2(acc[r][0], p1, wr01.x);
                    fma2(acc[r][1], p1, wr01.y);
                    fma2(acc[r][2], p1, wr23.x);
                    fma2(acc[r][3], p1, wr23.y);
                    fma2(acc[r][0], p2, wo01.x);
                    fma2(acc[r][1], p2, wo01.y);
                    fma2(acc[r][2], p2, wo23.x);
                    fma2(acc[r][3], p2, wo23.y);
                }
            }
        }

#pragma unroll
        for (int r = 0; r < 4; r++) {
            int grow = row0 + r0 + r;
            if (grow < N_NODES) {
                float2 f0 = up2(acc[r][0]);
                float2 f1 = up2(acc[r][1]);
                float2 f2 = up2(acc[r][2]);
                float2 f3 = up2(acc[r][3]);
                float4 o0, o1;
                o0.x = fmaxf(f0.x, 0.f); o0.y = fmaxf(f0.y, 0.f);
                o0.z = fmaxf(f1.x, 0.f); o0.w = fmaxf(f1.y, 0.f);
                o1.x = fmaxf(f2.x, 0.f); o1.y = fmaxf(f2.y, 0.f);
                o1.z = fmaxf(f3.x, 0.f); o1.w = fmaxf(f3.y, 0.f);
                float4* dst = (float4*)(O + (size_t)grow * 128 + c0);
                dst[0] = o0;
                dst[1] = o1;
            }
        }
    }
}

// ---------------- pooling (batch is sorted: strip-reduce then few atomics) ----
__global__ void k_pool_init() {
    int i = blockIdx.x * blockDim.x + threadIdx.x;
    if (i < NG * FDIM) { g_gmax[i] = 0; g_gsum[i] = 0.f; }
    if (i < NG) g_gcnt[i] = 0;
}

__device__ __forceinline__ void pool_flush(int gph, int lane, float4 mx, float4 sm, int cnt) {
    int base = gph * FDIM + lane * 4;
    atomicMax(&g_gmax[base + 0], __float_as_int(mx.x));
    atomicMax(&g_gmax[base + 1], __float_as_int(mx.y));
    atomicMax(&g_gmax[base + 2], __float_as_int(mx.z));
    atomicMax(&g_gmax[base + 3], __float_as_int(mx.w));
    atomicAdd(&g_gsum[base + 0], sm.x);
    atomicAdd(&g_gsum[base + 1], sm.y);
    atomicAdd(&g_gsum[base + 2], sm.z);
    atomicAdd(&g_gsum[base + 3], sm.w);
    if (lane == 0) atomicAdd(&g_gcnt[gph], cnt);
}

__global__ void k_pool(const int* __restrict__ batch) {
    const float4* __restrict__ h = (const float4*)g_h0;  // final layer output
    int w = (blockIdx.x * blockDim.x + threadIdx.x) >> 5;
    int lane = threadIdx.x & 31;
    if (w >= N_NODES / 32) return;
    int n0 = w * 32;
    int cur = batch[n0];
    float4 mx = make_float4(0.f, 0.f, 0.f, 0.f);
    float4 sm = make_float4(0.f, 0.f, 0.f, 0.f);
    int cnt = 0;
    for (int i = 0; i < 32; i++) {
        int n = n0 + i;
        int b = batch[n];
        if (b != cur) {
            pool_flush(cur, lane, mx, sm, cnt);
            mx = make_float4(0.f, 0.f, 0.f, 0.f);
            sm = make_float4(0.f, 0.f, 0.f, 0.f);
            cnt = 0;
            cur = b;
        }
        float4 v = h[(size_t)n * 32 + lane];
        mx.x = fmaxf(mx.x, v.x); mx.y = fmaxf(mx.y, v.y);
        mx.z = fmaxf(mx.z, v.z); mx.w = fmaxf(mx.w, v.w);
        sm.x += v.x; sm.y += v.y; sm.z += v.z; sm.w += v.w;
        cnt++;
    }
    pool_flush(cur, lane, mx, sm, cnt);
}

// ---------------- MLP head ----------------
__global__ void k_headg() {
    int gph = blockIdx.x;
    int c = threadIdx.x;
    float v;
    if (c < 128) {
        v = __int_as_float(g_gmax[gph * 128 + c]);
    } else {
        int cnt = g_gcnt[gph];
        float fc = (float)(cnt > 1 ? cnt : 1);
        v = g_gsum[gph * 128 + (c - 128)] / fc;
    }
    g_gvec[gph * 256 + c] = v;
}

__global__ void k_head1(const float* __restrict__ lw1, const float* __restrict__ lb1) {
    __shared__ float row[256];
    int gph = blockIdx.x, c = threadIdx.x;
    row[c] = g_gvec[gph * 256 + c];
    row[c + 128] = g_gvec[gph * 256 + c + 128];
    __syncthreads();
    float acc = lb1[c];
#pragma unroll 8
    for (int k = 0; k < 256; k++) acc += row[k] * lw1[k * 128 + c];
    g_m1[gph * 128 + c] = fmaxf(acc, 0.f);
}

__global__ void k_head2(const float* __restrict__ lw2, const float* __restrict__ lb2) {
    __shared__ float row[128];
    int gph = blockIdx.x, c = threadIdx.x;
    row[c] = g_m1[gph * 128 + c];
    row[c + 64] = g_m1[gph * 128 + c + 64];
    __syncthreads();
    float acc = lb2[c];
#pragma unroll 8
    for (int k = 0; k < 128; k++) acc += row[k] * lw2[k * 64 + c];
    g_m2[gph * 64 + c] = fmaxf(acc, 0.f);
}

__global__ void k_head3(const float* __restrict__ lw3, const float* __restrict__ lb3) {
    int gph = blockIdx.x, l = threadIdx.x;
    if (l >= NL) return;
    float acc = lb3[l];
#pragma unroll 8
    for (int k = 0; k < 64; k++) acc += g_m2[gph * 64 + k] * lw3[k * NL + l];
    g_z[gph * NL + l] = acc;
}

__global__ void k_softmax(float* __restrict__ out) {
    int l = threadIdx.x;
    if (l >= NL) return;
    float m = -1e30f;
    for (int gph = 0; gph < NG; gph++) m = fmaxf(m, g_z[gph * NL + l]);
    float s = 0.f;
    for (int gph = 0; gph < NG; gph++) s += expf(g_z[gph * NL + l] - m);
    float ls = m + logf(s);
    for (int gph = 0; gph < NG; gph++) out[gph * NL + l] = g_z[gph * NL + l] - ls;
}

// ---------------- launch ----------------
extern "C" void kernel_launch(void* const* d_in, const int* in_sizes, int n_in,
                              void* d_out, int out_size) {
    const int*   x       = (const int*)d_in[0];
    const int*   ei      = (const int*)d_in[1];
    const int*   batch   = (const int*)d_in[2];
    const float* emb     = (const float*)d_in[3];
    const float* w1_rel  = (const float*)d_in[4];
    const float* w1_root = (const float*)d_in[5];
    const float* b1      = (const float*)d_in[6];
    const float* w2_rel  = (const float*)d_in[7];
    const float* w2_root = (const float*)d_in[8];
    const float* b2      = (const float*)d_in[9];
    const float* lw1     = (const float*)d_in[10];
    const float* lb1     = (const float*)d_in[11];
    const float* lw2     = (const float*)d_in[12];
    const float* lb2     = (const float*)d_in[13];
    const float* lw3     = (const float*)d_in[14];
    const float* lb3     = (const float*)d_in[15];
    const int* src = ei;
    const int* dst = ei + N_EDGES;
    float* out = (float*)d_out;

    cudaFuncSetAttribute(k_gemm, cudaFuncAttributeMaxDynamicSharedMemorySize, GEMM_SMEM);

    k_gather<<<12500, 256>>>(x, (const float4*)emb);

    // CSR build (shared by both layers)
    k_zero_deg<<<SCAN_NB, 256>>>();
    k_count<<<N_EDGES / 256, 256>>>(dst);
    k_scan1<<<SCAN_NB, 256>>>();
    k_scan2<<<1, 512>>>();
    k_scan3<<<SCAN_NB, 256>>>();
    k_fill<<<N_EDGES / 256, 256>>>(src, dst);

    // layer 1
    k_aggregate<<<12500, 256>>>(0);
    k_gemm<<<148, 256, GEMM_SMEM>>>(w1_rel, w1_root, b1, 0);
    // layer 2
    k_aggregate<<<12500, 256>>>(1);
    k_gemm<<<148, 256, GEMM_SMEM>>>(w2_rel, w2_root, b2, 1);

    // pooling
    k_pool_init<<<32, 256>>>();
    k_pool<<<SCAN_NB, 256>>>(batch);

    // head
    k_headg<<<NG, 256>>>();
    k_head1<<<NG, 128>>>(lw1, lb1);
    k_head2<<<NG, 64>>>(lw2, lb2);
    k_head3<<<NG, 32>>>(lw3, lb3);
    k_softmax<<<1, 32>>>(out);
}